// round 2
// baseline (speedup 1.0000x reference)
#include <cuda_runtime.h>

// Problem constants (fixed shapes for this problem instance)
#define NB    32      // batch N
#define CLOC  512     // local channels C
#define HH    14
#define WW    14
#define HW2   196     // H*W
#define NHW   6272    // N*H*W
#define DGLB  2048    // global feature dim D
#define HIDN  256     // hidden dim
#define EPSC  1e-10f

// Scratch (device globals; no allocation allowed)
__device__ float g_hloc[NHW * HIDN];    // 6.4 MB: lf @ W1[D:]
__device__ float g_hglb[NB * HIDN];     // gf @ W1[:D] + b1
__device__ float g_scores[NB * NHW];    // 0.8 MB score matrix

// ---------------------------------------------------------------------------
// h_glb[i,o] = sum_k gf[i,k] * W1[k,o] + b1[o]      (32 x 2048 @ 2048 x 256)
// ---------------------------------------------------------------------------
__global__ void hglb_kernel(const float* __restrict__ gf,
                            const float* __restrict__ W1,
                            const float* __restrict__ b1) {
    int i = blockIdx.x;          // 0..31
    int o = threadIdx.x;         // 0..255
    const float* g = gf + i * DGLB;
    float s0 = 0.f, s1 = 0.f, s2 = 0.f, s3 = 0.f;
    #pragma unroll 4
    for (int k = 0; k < DGLB; k += 4) {
        s0 += g[k + 0] * W1[(k + 0) * HIDN + o];
        s1 += g[k + 1] * W1[(k + 1) * HIDN + o];
        s2 += g[k + 2] * W1[(k + 2) * HIDN + o];
        s3 += g[k + 3] * W1[(k + 3) * HIDN + o];
    }
    g_hglb[i * HIDN + o] = (s0 + s1) + (s2 + s3) + b1[o];
}

// ---------------------------------------------------------------------------
// h_loc = lf @ W1[D:]   (6272 x 512 @ 512 x 256), lf gathered from NCHW
// SGEMM tile: BM=64 (j), BN=256 (full HID), BK=32. 256 threads, 8x8 per thread.
// ---------------------------------------------------------------------------
__global__ __launch_bounds__(256) void hloc_kernel(const float* __restrict__ LF,
                                                   const float* __restrict__ W1loc) {
    __shared__ float As[64][33];     // [m][k], padded
    __shared__ float Bs[32][256];    // [k][n]
    const int j0  = blockIdx.x * 64;
    const int tid = threadIdx.x;
    const int tm  = tid >> 5;        // 0..7 (warp id) -> owns rows tm*8..tm*8+7
    const int tn  = tid & 31;        // lane -> col groups tn*4 and 128+tn*4

    // A-load mapping: thread = (m = tid&63, kq = tid>>6); coalesced along m (pos dim)
    const int am  = tid & 63;
    const int akq = tid >> 6;        // 0..3
    const int j   = j0 + am;
    const int n_  = j / HW2;
    const int pos = j % HW2;
    const long abase = (long)n_ * CLOC * HW2 + pos;

    // B-load mapping: thread = (n4 = tid&63, kq = tid>>6); float4 coalesced
    const int bn4 = tid & 63;
    const int bkq = tid >> 6;

    float acc[8][8];
    #pragma unroll
    for (int a = 0; a < 8; a++)
        #pragma unroll
        for (int b = 0; b < 8; b++) acc[a][b] = 0.f;

    for (int kc = 0; kc < CLOC; kc += 32) {
        #pragma unroll
        for (int r = 0; r < 8; r++) {
            int k = akq * 8 + r;
            As[am][k] = LF[abase + (long)(kc + k) * HW2];
        }
        #pragma unroll
        for (int r = 0; r < 8; r++) {
            int k = bkq + 4 * r;
            *(float4*)&Bs[k][bn4 * 4] =
                *(const float4*)&W1loc[(kc + k) * HIDN + bn4 * 4];
        }
        __syncthreads();
        #pragma unroll
        for (int k = 0; k < 32; k++) {
            float a[8];
            #pragma unroll
            for (int im = 0; im < 8; im++) a[im] = As[tm * 8 + im][k];  // broadcast
            float4 b0 = *(float4*)&Bs[k][tn * 4];
            float4 b1 = *(float4*)&Bs[k][128 + tn * 4];
            #pragma unroll
            for (int im = 0; im < 8; im++) {
                acc[im][0] += a[im] * b0.x; acc[im][1] += a[im] * b0.y;
                acc[im][2] += a[im] * b0.z; acc[im][3] += a[im] * b0.w;
                acc[im][4] += a[im] * b1.x; acc[im][5] += a[im] * b1.y;
                acc[im][6] += a[im] * b1.z; acc[im][7] += a[im] * b1.w;
            }
        }
        __syncthreads();
    }
    #pragma unroll
    for (int im = 0; im < 8; im++) {
        int m = j0 + tm * 8 + im;
        float4 v0 = make_float4(acc[im][0], acc[im][1], acc[im][2], acc[im][3]);
        float4 v1 = make_float4(acc[im][4], acc[im][5], acc[im][6], acc[im][7]);
        *(float4*)&g_hloc[m * HIDN + tn * 4]       = v0;
        *(float4*)&g_hloc[m * HIDN + 128 + tn * 4] = v1;
    }
}

// ---------------------------------------------------------------------------
// Fused main kernel: for pair (i, j-tile of 64):
//   h1 = relu(h_glb[i] + h_loc[j])        (built in smem on the fly)
//   h2 = relu(h1 @ W2 + b2)               (SGEMM in registers)
//   scores[i,j] = h2 . W3 + b3            (register epilogue + warp reduce)
// ---------------------------------------------------------------------------
__global__ __launch_bounds__(256) void score_kernel(const float* __restrict__ W2,
                                                    const float* __restrict__ b2,
                                                    const float* __restrict__ W3,
                                                    const float* __restrict__ b3p) {
    __shared__ float As[64][33];
    __shared__ float Bs[32][256];
    const int j0  = blockIdx.x * 64;
    const int i   = blockIdx.y;
    const int tid = threadIdx.x;
    const int tm  = tid >> 5;
    const int tn  = tid & 31;

    // A-load mapping: thread = (k = tid&31, mq = tid>>5); coalesced along k
    const int ak  = tid & 31;
    const int amq = tid >> 5;        // 0..7
    const float* grow = g_hglb + i * HIDN;

    const int bn4 = tid & 63;
    const int bkq = tid >> 6;

    float acc[8][8];
    #pragma unroll
    for (int a = 0; a < 8; a++)
        #pragma unroll
        for (int b = 0; b < 8; b++) acc[a][b] = 0.f;

    for (int kc = 0; kc < HIDN; kc += 32) {
        float gv = grow[kc + ak];
        #pragma unroll
        for (int r = 0; r < 8; r++) {
            int m = amq * 8 + r;
            As[m][ak] = fmaxf(g_hloc[(j0 + m) * HIDN + kc + ak] + gv, 0.f);
        }
        #pragma unroll
        for (int r = 0; r < 8; r++) {
            int k = bkq + 4 * r;
            *(float4*)&Bs[k][bn4 * 4] =
                *(const float4*)&W2[(kc + k) * HIDN + bn4 * 4];
        }
        __syncthreads();
        #pragma unroll
        for (int k = 0; k < 32; k++) {
            float a[8];
            #pragma unroll
            for (int im = 0; im < 8; im++) a[im] = As[tm * 8 + im][k];  // broadcast
            float4 b0 = *(float4*)&Bs[k][tn * 4];
            float4 b1 = *(float4*)&Bs[k][128 + tn * 4];
            #pragma unroll
            for (int im = 0; im < 8; im++) {
                acc[im][0] += a[im] * b0.x; acc[im][1] += a[im] * b0.y;
                acc[im][2] += a[im] * b0.z; acc[im][3] += a[im] * b0.w;
                acc[im][4] += a[im] * b1.x; acc[im][5] += a[im] * b1.y;
                acc[im][6] += a[im] * b1.z; acc[im][7] += a[im] * b1.w;
            }
        }
        __syncthreads();
    }

    // Epilogue: relu(acc + b2) . W3, warp-reduce per row
    float w3v[8], bb[8];
    #pragma unroll
    for (int q = 0; q < 4; q++) {
        w3v[q]     = W3[tn * 4 + q];
        bb[q]      = b2[tn * 4 + q];
        w3v[4 + q] = W3[128 + tn * 4 + q];
        bb[4 + q]  = b2[128 + tn * 4 + q];
    }
    const float b3v = b3p[0];
    #pragma unroll
    for (int im = 0; im < 8; im++) {
        float s = 0.f;
        #pragma unroll
        for (int q = 0; q < 8; q++)
            s += fmaxf(acc[im][q] + bb[q], 0.f) * w3v[q];
        #pragma unroll
        for (int off = 16; off; off >>= 1)
            s += __shfl_xor_sync(0xffffffffu, s, off);
        if (tn == 0)
            g_scores[i * NHW + j0 + tm * 8 + im] = s + b3v;
    }
}

// ---------------------------------------------------------------------------
// Per-row softmax-style finalize:
//   mx = max_j scores[i,j]
//   neg_mean = sum_{j not in own block} exp(s-mx) / (nhw-hw) + EPS
//   out[i,p] = scores[i, i*hw+p] - mx - log(neg_mean)
// ---------------------------------------------------------------------------
__global__ void finalize_kernel(float* __restrict__ out) {
    const int i   = blockIdx.x;
    const int tid = threadIdx.x;     // 256
    __shared__ float red[256];
    const float* row = g_scores + i * NHW;

    float mx = -1e30f;
    for (int jj = tid; jj < NHW; jj += 256) mx = fmaxf(mx, row[jj]);
    red[tid] = mx;
    __syncthreads();
    for (int s = 128; s; s >>= 1) {
        if (tid < s) red[tid] = fmaxf(red[tid], red[tid + s]);
        __syncthreads();
    }
    mx = red[0];
    __syncthreads();

    const int lo = i * HW2, hi = lo + HW2;
    float sum = 0.f;
    for (int jj = tid; jj < NHW; jj += 256) {
        if (jj < lo || jj >= hi) sum += __expf(row[jj] - mx);
    }
    red[tid] = sum;
    __syncthreads();
    for (int s = 128; s; s >>= 1) {
        if (tid < s) red[tid] += red[tid + s];
        __syncthreads();
    }
    const float neg_mean = red[0] / (float)(NHW - HW2) + EPSC;
    const float lg = __logf(neg_mean);

    for (int p = tid; p < HW2; p += 256)
        out[i * HW2 + p] = row[lo + p] - mx - lg;
}

// ---------------------------------------------------------------------------
extern "C" void kernel_launch(void* const* d_in, const int* in_sizes, int n_in,
                              void* d_out, int out_size) {
    const float* LF = (const float*)d_in[0];   // (32,512,14,14)
    const float* GF = (const float*)d_in[1];   // (32,2048,1,1)
    const float* W1 = (const float*)d_in[2];   // (2560,256)
    const float* b1 = (const float*)d_in[3];   // (256,)
    const float* W2 = (const float*)d_in[4];   // (256,256)
    const float* b2 = (const float*)d_in[5];   // (256,)
    const float* W3 = (const float*)d_in[6];   // (256,1)
    const float* b3 = (const float*)d_in[7];   // (1,)
    float* out = (float*)d_out;                // (32,14,14)

    hglb_kernel<<<NB, HIDN>>>(GF, W1, b1);
    hloc_kernel<<<NHW / 64, 256>>>(LF, W1 + (long)DGLB * HIDN);
    score_kernel<<<dim3(NHW / 64, NB), 256>>>(W2, b2, W3, b3);
    finalize_kernel<<<NB, 256>>>(out);
}

// round 5
// speedup vs baseline: 2.0428x; 2.0428x over previous
#include <cuda_runtime.h>
#include <cstdint>

// Problem constants
#define NB    32
#define CLOC  512
#define HW2   196
#define NHW   6272
#define DGLB  2048
#define HIDN  256
#define EPSC  1e-10f

// Scratch (device globals; no allocation allowed)
__device__ float g_hloc[NHW * HIDN];     // 6.4 MB
__device__ float g_hglb[NB * HIDN];
__device__ float g_scores[NB * NHW];     // 0.8 MB

// ---------------------------------------------------------------------------
// helpers
// ---------------------------------------------------------------------------
__device__ __forceinline__ float tf32r(float x) {
    float y;
    asm("cvt.rna.tf32.f32 %0, %1;" : "=f"(y) : "f"(x));
    return y;
}
__device__ __forceinline__ void mma8(float* c, const uint32_t* a,
                                     uint32_t b0, uint32_t b1) {
    asm volatile(
        "mma.sync.aligned.m16n8k8.row.col.f32.tf32.tf32.f32 "
        "{%0,%1,%2,%3}, {%4,%5,%6,%7}, {%8,%9}, {%0,%1,%2,%3};"
        : "+f"(c[0]), "+f"(c[1]), "+f"(c[2]), "+f"(c[3])
        : "r"(a[0]), "r"(a[1]), "r"(a[2]), "r"(a[3]), "r"(b0), "r"(b1));
}

// ---------------------------------------------------------------------------
// h_glb[i,o] = gf[i] . W1[:D, o] + b1[o]
// ---------------------------------------------------------------------------
__global__ void hglb_kernel(const float* __restrict__ gf,
                            const float* __restrict__ W1,
                            const float* __restrict__ b1) {
    int i = blockIdx.x;
    int o = threadIdx.x;
    const float* g = gf + i * DGLB;
    float s0 = 0.f, s1 = 0.f, s2 = 0.f, s3 = 0.f;
    #pragma unroll 4
    for (int k = 0; k < DGLB; k += 4) {
        s0 += g[k + 0] * W1[(k + 0) * HIDN + o];
        s1 += g[k + 1] * W1[(k + 1) * HIDN + o];
        s2 += g[k + 2] * W1[(k + 2) * HIDN + o];
        s3 += g[k + 3] * W1[(k + 3) * HIDN + o];
    }
    g_hglb[i * HIDN + o] = (s0 + s1) + (s2 + s3) + b1[o];
}

// ---------------------------------------------------------------------------
// h_loc = lf @ W1[D:]  (6272 x 512 @ 512 x 256), fp32 SGEMM (exact)
// ---------------------------------------------------------------------------
__global__ __launch_bounds__(256) void hloc_kernel(const float* __restrict__ LF,
                                                   const float* __restrict__ W1loc) {
    __shared__ float As[64][33];
    __shared__ float Bs[32][256];
    const int j0  = blockIdx.x * 64;
    const int tid = threadIdx.x;
    const int tm  = tid >> 5;
    const int tn  = tid & 31;
    const int am  = tid & 63;
    const int akq = tid >> 6;
    const int j   = j0 + am;
    const int n_  = j / HW2;
    const int pos = j % HW2;
    const long abase = (long)n_ * CLOC * HW2 + pos;
    const int bn4 = tid & 63;
    const int bkq = tid >> 6;

    float acc[8][8];
    #pragma unroll
    for (int a = 0; a < 8; a++)
        #pragma unroll
        for (int b = 0; b < 8; b++) acc[a][b] = 0.f;

    for (int kc = 0; kc < CLOC; kc += 32) {
        #pragma unroll
        for (int r = 0; r < 8; r++) {
            int k = akq * 8 + r;
            As[am][k] = LF[abase + (long)(kc + k) * HW2];
        }
        #pragma unroll
        for (int r = 0; r < 8; r++) {
            int k = bkq + 4 * r;
            *(float4*)&Bs[k][bn4 * 4] = *(const float4*)&W1loc[(kc + k) * HIDN + bn4 * 4];
        }
        __syncthreads();
        #pragma unroll
        for (int k = 0; k < 32; k++) {
            float a[8];
            #pragma unroll
            for (int im = 0; im < 8; im++) a[im] = As[tm * 8 + im][k];
            float4 b0 = *(float4*)&Bs[k][tn * 4];
            float4 b1 = *(float4*)&Bs[k][128 + tn * 4];
            #pragma unroll
            for (int im = 0; im < 8; im++) {
                acc[im][0] += a[im] * b0.x; acc[im][1] += a[im] * b0.y;
                acc[im][2] += a[im] * b0.z; acc[im][3] += a[im] * b0.w;
                acc[im][4] += a[im] * b1.x; acc[im][5] += a[im] * b1.y;
                acc[im][6] += a[im] * b1.z; acc[im][7] += a[im] * b1.w;
            }
        }
        __syncthreads();
    }
    #pragma unroll
    for (int im = 0; im < 8; im++) {
        int m = j0 + tm * 8 + im;
        float4 v0 = make_float4(acc[im][0], acc[im][1], acc[im][2], acc[im][3]);
        float4 v1 = make_float4(acc[im][4], acc[im][5], acc[im][6], acc[im][7]);
        *(float4*)&g_hloc[m * HIDN + tn * 4]       = v0;
        *(float4*)&g_hloc[m * HIDN + 128 + tn * 4] = v1;
    }
}

// ---------------------------------------------------------------------------
// score kernel: warp-level tf32 mma.sync (sm_80+ path; tcgen05 unavailable
// because the harness compiles to the plain sm_103 family target).
// CTA = (j-tile of 128, i). A = relu(hglb[i]+hloc[j]) [128 x 64 per chunk],
// B = W2 chunk [64 x 256] in natural [k][n] layout. fp32 accumulate.
// 8 warps = 2(m) x 4(n); warp tile 64m x 64n = 4 x 8 mma tiles.
// ---------------------------------------------------------------------------
#define AS_STRIDE 68
#define BS_STRIDE 264
#define AS_OFF 0
#define AS_BYTES (128 * AS_STRIDE * 4)              // 34816
#define BS_OFF AS_BYTES
#define BS_BYTES (64 * BS_STRIDE * 4)               // 67584
#define B2_OFF (BS_OFF + BS_BYTES)                  // 102400
#define W3_OFF (B2_OFF + 1024)
#define RED_OFF (W3_OFF + 1024)
#define SM_TOTAL (RED_OFF + 128 * 4 * 4)            // 106496

__global__ __launch_bounds__(256, 1) void score_mma(const float* __restrict__ W2,
                                                    const float* __restrict__ b2,
                                                    const float* __restrict__ W3,
                                                    const float* __restrict__ b3p) {
    extern __shared__ char smem[];
    float*    AsF = (float*)(smem + AS_OFF);
    float*    BsF = (float*)(smem + BS_OFF);
    const uint32_t* AsU = (const uint32_t*)(smem + AS_OFF);
    const uint32_t* BsU = (const uint32_t*)(smem + BS_OFF);
    float* b2s = (float*)(smem + B2_OFF);
    float* w3s = (float*)(smem + W3_OFF);
    float* red = (float*)(smem + RED_OFF);

    const int tid = threadIdx.x;
    const int wid = tid >> 5, lid = tid & 31;
    const int g   = lid >> 2, tig = lid & 3;         // mma fragment coords
    const int j0  = blockIdx.x * 128;
    const int i   = blockIdx.y;
    const int m0w = (wid & 1) * 64;                  // warp m-base
    const int nw  = wid >> 1;                        // warp n-index 0..3
    const int n0w = nw * 64;                         // warp n-base

    b2s[tid] = b2[tid];
    w3s[tid] = W3[tid];

    // fill-phase thread mappings
    const int k4 = tid & 15;                         // A: k = k4*4
    const int mrow = tid >> 4;                       // A: m rows mrow, mrow+16, ...
    const int bn4 = tid & 63;                        // B: n = bn4*4
    const int bk  = tid >> 6;                        // B: k rows bk, bk+4, ...

    const float* hl = g_hloc + (long)j0 * HIDN;

    float acc[4][8][4];
    #pragma unroll
    for (int mt = 0; mt < 4; mt++)
        #pragma unroll
        for (int nt = 0; nt < 8; nt++)
            #pragma unroll
            for (int q = 0; q < 4; q++) acc[mt][nt][q] = 0.f;

    for (int kc = 0; kc < 4; kc++) {
        const int kb = kc * 64;
        // ---- A build: relu(hloc + hglb), tf32-rounded ----
        float4 gv = *(const float4*)(g_hglb + i * HIDN + kb + k4 * 4);
        #pragma unroll
        for (int r = 0; r < 8; r++) {
            int m = mrow + r * 16;
            float4 v = *(const float4*)(hl + (long)m * HIDN + kb + k4 * 4);
            float* dst = AsF + m * AS_STRIDE + k4 * 4;
            dst[0] = tf32r(fmaxf(v.x + gv.x, 0.f));
            dst[1] = tf32r(fmaxf(v.y + gv.y, 0.f));
            dst[2] = tf32r(fmaxf(v.z + gv.z, 0.f));
            dst[3] = tf32r(fmaxf(v.w + gv.w, 0.f));
        }
        // ---- B fill: W2 chunk, tf32-rounded ----
        #pragma unroll
        for (int r = 0; r < 16; r++) {
            int k = bk + r * 4;
            float4 v = *(const float4*)(W2 + (long)(kb + k) * HIDN + bn4 * 4);
            float* dst = BsF + k * BS_STRIDE + bn4 * 4;
            dst[0] = tf32r(v.x);
            dst[1] = tf32r(v.y);
            dst[2] = tf32r(v.z);
            dst[3] = tf32r(v.w);
        }
        __syncthreads();

        // ---- mma phase ----
        #pragma unroll
        for (int k8 = 0; k8 < 8; k8++) {
            const int kk = k8 * 8;
            uint32_t a[4][4];
            #pragma unroll
            for (int mt = 0; mt < 4; mt++) {
                int mr = m0w + mt * 16 + g;
                a[mt][0] = AsU[mr * AS_STRIDE + kk + tig];
                a[mt][1] = AsU[(mr + 8) * AS_STRIDE + kk + tig];
                a[mt][2] = AsU[mr * AS_STRIDE + kk + tig + 4];
                a[mt][3] = AsU[(mr + 8) * AS_STRIDE + kk + tig + 4];
            }
            #pragma unroll
            for (int nt = 0; nt < 8; nt++) {
                int nc = n0w + nt * 8 + g;
                uint32_t b0 = BsU[(kk + tig) * BS_STRIDE + nc];
                uint32_t b1 = BsU[(kk + tig + 4) * BS_STRIDE + nc];
                #pragma unroll
                for (int mt = 0; mt < 4; mt++)
                    mma8(acc[mt][nt], a[mt], b0, b1);
            }
        }
        __syncthreads();
    }

    // ---- epilogue: relu(acc + b2) . W3, reduce n across lanes/warps ----
    #pragma unroll
    for (int mt = 0; mt < 4; mt++) {
        float s0 = 0.f, s1 = 0.f;
        #pragma unroll
        for (int nt = 0; nt < 8; nt++) {
            int n = n0w + nt * 8 + 2 * tig;
            float w0 = w3s[n], w1 = w3s[n + 1];
            float c0 = b2s[n], c1 = b2s[n + 1];
            s0 += fmaxf(acc[mt][nt][0] + c0, 0.f) * w0
                + fmaxf(acc[mt][nt][1] + c1, 0.f) * w1;
            s1 += fmaxf(acc[mt][nt][2] + c0, 0.f) * w0
                + fmaxf(acc[mt][nt][3] + c1, 0.f) * w1;
        }
        s0 += __shfl_xor_sync(0xffffffffu, s0, 1);
        s0 += __shfl_xor_sync(0xffffffffu, s0, 2);
        s1 += __shfl_xor_sync(0xffffffffu, s1, 1);
        s1 += __shfl_xor_sync(0xffffffffu, s1, 2);
        if (tig == 0) {
            red[(m0w + mt * 16 + g) * 4 + nw]     = s0;
            red[(m0w + mt * 16 + g + 8) * 4 + nw] = s1;
        }
    }
    __syncthreads();
    if (tid < 128) {
        float s = red[tid * 4] + red[tid * 4 + 1] + red[tid * 4 + 2] + red[tid * 4 + 3];
        g_scores[i * NHW + j0 + tid] = s + b3p[0];
    }
}

// ---------------------------------------------------------------------------
// finalize (unchanged)
// ---------------------------------------------------------------------------
__global__ void finalize_kernel(float* __restrict__ out) {
    const int i   = blockIdx.x;
    const int tid = threadIdx.x;
    __shared__ float red[256];
    const float* row = g_scores + i * NHW;

    float mx = -1e30f;
    for (int jj = tid; jj < NHW; jj += 256) mx = fmaxf(mx, row[jj]);
    red[tid] = mx;
    __syncthreads();
    for (int s = 128; s; s >>= 1) {
        if (tid < s) red[tid] = fmaxf(red[tid], red[tid + s]);
        __syncthreads();
    }
    mx = red[0];
    __syncthreads();

    const int lo = i * HW2, hi = lo + HW2;
    float sum = 0.f;
    for (int jj = tid; jj < NHW; jj += 256) {
        if (jj < lo || jj >= hi) sum += __expf(row[jj] - mx);
    }
    red[tid] = sum;
    __syncthreads();
    for (int s = 128; s; s >>= 1) {
        if (tid < s) red[tid] += red[tid + s];
        __syncthreads();
    }
    const float neg_mean = red[0] / (float)(NHW - HW2) + EPSC;
    const float lg = __logf(neg_mean);

    for (int p = tid; p < HW2; p += 256)
        out[i * HW2 + p] = row[lo + p] - mx - lg;
}

// ---------------------------------------------------------------------------
extern "C" void kernel_launch(void* const* d_in, const int* in_sizes, int n_in,
                              void* d_out, int out_size) {
    const float* LF = (const float*)d_in[0];
    const float* GF = (const float*)d_in[1];
    const float* W1 = (const float*)d_in[2];
    const float* b1 = (const float*)d_in[3];
    const float* W2 = (const float*)d_in[4];
    const float* b2 = (const float*)d_in[5];
    const float* W3 = (const float*)d_in[6];
    const float* b3 = (const float*)d_in[7];
    float* out = (float*)d_out;

    static int attr_done = 0;
    if (!attr_done) {
        cudaFuncSetAttribute(score_mma, cudaFuncAttributeMaxDynamicSharedMemorySize, SM_TOTAL);
        attr_done = 1;
    }

    hglb_kernel<<<NB, HIDN>>>(GF, W1, b1);
    hloc_kernel<<<NHW / 64, 256>>>(LF, W1 + (long)DGLB * HIDN);
    score_mma<<<dim3(NHW / 128, NB), 256, SM_TOTAL>>>(W2, b2, W3, b3);
    finalize_kernel<<<NB, 256>>>(out);
}

// round 6
// speedup vs baseline: 2.3306x; 1.1409x over previous
#include <cuda_runtime.h>
#include <cstdint>

// Problem constants
#define NB    32
#define CLOC  512
#define HW2   196
#define NHW   6272
#define DGLB  2048
#define HIDN  256
#define EPSC  1e-10f

// Scratch (device globals; no allocation allowed)
__device__ float g_hloc[NHW * HIDN];     // 6.4 MB
__device__ float g_hglb[NB * HIDN];
__device__ float g_scores[NB * NHW];     // 0.8 MB
__device__ float g_W2tf[HIDN * HIDN];    // W2 pre-rounded to tf32

// ---------------------------------------------------------------------------
// helpers
// ---------------------------------------------------------------------------
__device__ __forceinline__ float tf32r(float x) {
    float y;
    asm("cvt.rna.tf32.f32 %0, %1;" : "=f"(y) : "f"(x));
    return y;
}
__device__ __forceinline__ void mma8(float* c, const uint32_t* a,
                                     uint32_t b0, uint32_t b1) {
    asm volatile(
        "mma.sync.aligned.m16n8k8.row.col.f32.tf32.tf32.f32 "
        "{%0,%1,%2,%3}, {%4,%5,%6,%7}, {%8,%9}, {%0,%1,%2,%3};"
        : "+f"(c[0]), "+f"(c[1]), "+f"(c[2]), "+f"(c[3])
        : "r"(a[0]), "r"(a[1]), "r"(a[2]), "r"(a[3]), "r"(b0), "r"(b1));
}
__device__ __forceinline__ uint32_t smem_u32(const void* p) {
    uint32_t a;
    asm("{ .reg .u64 t; cvta.to.shared.u64 t, %1; cvt.u32.u64 %0, t; }" : "=r"(a) : "l"(p));
    return a;
}
__device__ __forceinline__ void cpa16(uint32_t dst, const void* src) {
    asm volatile("cp.async.ca.shared.global [%0], [%1], 16;" :: "r"(dst), "l"(src));
}
#define CPA_COMMIT() asm volatile("cp.async.commit_group;" ::: "memory")
#define CPA_WAIT0()  asm volatile("cp.async.wait_group 0;" ::: "memory")

// ---------------------------------------------------------------------------
// prep: blocks 0..31 -> h_glb (K-split x4, 1024 thr); blocks 32..39 -> W2 tf32
// ---------------------------------------------------------------------------
__global__ __launch_bounds__(1024) void prep_kernel(const float* __restrict__ gf,
                                                    const float* __restrict__ W1,
                                                    const float* __restrict__ b1,
                                                    const float* __restrict__ W2) {
    const int tid = threadIdx.x;
    if (blockIdx.x < NB) {
        __shared__ float red[1024];
        const int i  = blockIdx.x;
        const int o  = tid & 255;
        const int kq = tid >> 8;                 // 0..3
        const float* g = gf + i * DGLB + kq * 512;
        const float* w = W1 + (long)(kq * 512) * HIDN + o;
        float s0 = 0.f, s1 = 0.f;
        #pragma unroll 8
        for (int k = 0; k < 512; k += 2) {
            s0 += g[k]     * w[(long)k * HIDN];
            s1 += g[k + 1] * w[(long)(k + 1) * HIDN];
        }
        red[tid] = s0 + s1;
        __syncthreads();
        if (tid < 256)
            g_hglb[i * HIDN + o] = red[tid] + red[tid + 256] + red[tid + 512]
                                 + red[tid + 768] + b1[o];
    } else {
        const int base = (blockIdx.x - NB) * 8192 + tid * 8;
        #pragma unroll
        for (int q = 0; q < 8; q++)
            g_W2tf[base + q] = tf32r(W2[base + q]);
    }
}

// ---------------------------------------------------------------------------
// h_loc = lf @ W1[D:]  (6272 x 512 @ 512 x 256), fp32 SGEMM (exact)
// ---------------------------------------------------------------------------
__global__ __launch_bounds__(256) void hloc_kernel(const float* __restrict__ LF,
                                                   const float* __restrict__ W1loc) {
    __shared__ float As[64][33];
    __shared__ float Bs[32][256];
    const int j0  = blockIdx.x * 64;
    const int tid = threadIdx.x;
    const int tm  = tid >> 5;
    const int tn  = tid & 31;
    const int am  = tid & 63;
    const int akq = tid >> 6;
    const int j   = j0 + am;
    const int n_  = j / HW2;
    const int pos = j % HW2;
    const long abase = (long)n_ * CLOC * HW2 + pos;
    const int bn4 = tid & 63;
    const int bkq = tid >> 6;

    float acc[8][8];
    #pragma unroll
    for (int a = 0; a < 8; a++)
        #pragma unroll
        for (int b = 0; b < 8; b++) acc[a][b] = 0.f;

    for (int kc = 0; kc < CLOC; kc += 32) {
        #pragma unroll
        for (int r = 0; r < 8; r++) {
            int k = akq * 8 + r;
            As[am][k] = LF[abase + (long)(kc + k) * HW2];
        }
        #pragma unroll
        for (int r = 0; r < 8; r++) {
            int k = bkq + 4 * r;
            *(float4*)&Bs[k][bn4 * 4] = *(const float4*)&W1loc[(kc + k) * HIDN + bn4 * 4];
        }
        __syncthreads();
        #pragma unroll
        for (int k = 0; k < 32; k++) {
            float a[8];
            #pragma unroll
            for (int im = 0; im < 8; im++) a[im] = As[tm * 8 + im][k];
            float4 b0 = *(float4*)&Bs[k][tn * 4];
            float4 b1 = *(float4*)&Bs[k][128 + tn * 4];
            #pragma unroll
            for (int im = 0; im < 8; im++) {
                acc[im][0] += a[im] * b0.x; acc[im][1] += a[im] * b0.y;
                acc[im][2] += a[im] * b0.z; acc[im][3] += a[im] * b0.w;
                acc[im][4] += a[im] * b1.x; acc[im][5] += a[im] * b1.y;
                acc[im][6] += a[im] * b1.z; acc[im][7] += a[im] * b1.w;
            }
        }
        __syncthreads();
    }
    #pragma unroll
    for (int im = 0; im < 8; im++) {
        int m = j0 + tm * 8 + im;
        float4 v0 = make_float4(acc[im][0], acc[im][1], acc[im][2], acc[im][3]);
        float4 v1 = make_float4(acc[im][4], acc[im][5], acc[im][6], acc[im][7]);
        *(float4*)&g_hloc[m * HIDN + tn * 4]       = v0;
        *(float4*)&g_hloc[m * HIDN + 128 + tn * 4] = v1;
    }
}

// ---------------------------------------------------------------------------
// score kernel: warp-level tf32 mma.sync, double-buffered + cp.async pipelined.
// CTA = (j-tile of 128, i). A = relu(hglb[i]+hloc[j]) [128 x 64 per chunk],
// B = g_W2tf chunk [64 x 256] (pre-rounded; raw cp.async copy).
// 8 warps = 2(m) x 4(n); warp tile 64m x 64n = 4 x 8 m16n8k8 mma tiles.
// ---------------------------------------------------------------------------
#define AS_STRIDE 68
#define BS_STRIDE 264
#define AS_BYTES (128 * AS_STRIDE * 4)              // 34816
#define BS_BYTES (64 * BS_STRIDE * 4)               // 67584
#define AS_OFF   0                                  // two buffers
#define BS_OFF   (2 * AS_BYTES)                     // 69632
#define B2_OFF   (BS_OFF + 2 * BS_BYTES)            // 204800
#define W3_OFF   (B2_OFF + 1024)
#define RED_OFF  (W3_OFF + 1024)
#define SM_TOTAL (RED_OFF + 128 * 4 * 4)            // 208896

__global__ __launch_bounds__(256, 1) void score_mma(const float* __restrict__ b2,
                                                    const float* __restrict__ W3,
                                                    const float* __restrict__ b3p) {
    extern __shared__ char smem[];
    float* b2s = (float*)(smem + B2_OFF);
    float* w3s = (float*)(smem + W3_OFF);
    float* red = (float*)(smem + RED_OFF);
    const uint32_t sbase = smem_u32(smem);

    const int tid = threadIdx.x;
    const int wid = tid >> 5, lid = tid & 31;
    const int g   = lid >> 2, tig = lid & 3;
    const int j0  = blockIdx.x * 128;
    const int i   = blockIdx.y;
    const int m0w = (wid & 1) * 64;
    const int nw  = wid >> 1;
    const int n0w = nw * 64;

    b2s[tid] = b2[tid];
    w3s[tid] = W3[tid];

    // fill-phase thread mappings
    const int k4   = tid & 15;                       // A: k = k4*4
    const int mrow = tid >> 4;                       // A rows: mrow + r*16
    const int bn4  = tid & 63;                       // B: n = bn4*4
    const int bk   = tid >> 6;                       // B rows: bk + r*4

    const float* hl = g_hloc + (long)j0 * HIDN;
    const float* gb = g_hglb + i * HIDN;

    float acc[4][8][4];
    #pragma unroll
    for (int mt = 0; mt < 4; mt++)
        #pragma unroll
        for (int nt = 0; nt < 8; nt++)
            #pragma unroll
            for (int q = 0; q < 4; q++) acc[mt][nt][q] = 0.f;

    // ---- initial fill: chunk 0 into buffer 0 ----
    {
        float4 gv = *(const float4*)(gb + k4 * 4);
        float* As0 = (float*)(smem + AS_OFF);
        #pragma unroll
        for (int r = 0; r < 8; r++) {
            int m = mrow + r * 16;
            float4 v = *(const float4*)(hl + (long)m * HIDN + k4 * 4);
            float* dst = As0 + m * AS_STRIDE + k4 * 4;
            dst[0] = tf32r(fmaxf(v.x + gv.x, 0.f));
            dst[1] = tf32r(fmaxf(v.y + gv.y, 0.f));
            dst[2] = tf32r(fmaxf(v.z + gv.z, 0.f));
            dst[3] = tf32r(fmaxf(v.w + gv.w, 0.f));
        }
        #pragma unroll
        for (int r = 0; r < 16; r++) {
            int k = bk + r * 4;
            cpa16(sbase + BS_OFF + (k * BS_STRIDE + bn4 * 4) * 4,
                  g_W2tf + (long)k * HIDN + bn4 * 4);
        }
        CPA_COMMIT();
        CPA_WAIT0();
        __syncthreads();
    }

    for (int c = 0; c < 4; c++) {
        const int pb = c & 1, nb = pb ^ 1;
        const uint32_t* AsU = (const uint32_t*)(smem + AS_OFF + pb * AS_BYTES);
        const uint32_t* BsU = (const uint32_t*)(smem + BS_OFF + pb * BS_BYTES);

        // ---- prefetch next chunk: A -> regs (LDG), B -> smem (cp.async) ----
        float4 areg[8];
        float4 gvn;
        if (c < 3) {
            const int kb = (c + 1) * 64;
            gvn = *(const float4*)(gb + kb + k4 * 4);
            #pragma unroll
            for (int r = 0; r < 8; r++) {
                int m = mrow + r * 16;
                areg[r] = *(const float4*)(hl + (long)m * HIDN + kb + k4 * 4);
            }
            #pragma unroll
            for (int r = 0; r < 16; r++) {
                int k = bk + r * 4;
                cpa16(sbase + BS_OFF + nb * BS_BYTES + (k * BS_STRIDE + bn4 * 4) * 4,
                      g_W2tf + (long)(kb + k) * HIDN + bn4 * 4);
            }
            CPA_COMMIT();
        }

        // ---- mma phase on current buffers ----
        #pragma unroll
        for (int k8 = 0; k8 < 8; k8++) {
            const int kk = k8 * 8;
            uint32_t a[4][4];
            #pragma unroll
            for (int mt = 0; mt < 4; mt++) {
                int mr = m0w + mt * 16 + g;
                a[mt][0] = AsU[mr * AS_STRIDE + kk + tig];
                a[mt][1] = AsU[(mr + 8) * AS_STRIDE + kk + tig];
                a[mt][2] = AsU[mr * AS_STRIDE + kk + tig + 4];
                a[mt][3] = AsU[(mr + 8) * AS_STRIDE + kk + tig + 4];
            }
            #pragma unroll
            for (int nt = 0; nt < 8; nt++) {
                int nc = n0w + nt * 8 + g;
                uint32_t b0 = BsU[(kk + tig) * BS_STRIDE + nc];
                uint32_t b1 = BsU[(kk + tig + 4) * BS_STRIDE + nc];
                #pragma unroll
                for (int mt = 0; mt < 4; mt++)
                    mma8(acc[mt][nt], a[mt], b0, b1);
            }
        }

        // ---- store prefetched A into next buffer; wait B; barrier ----
        if (c < 3) {
            float* AsN = (float*)(smem + AS_OFF + nb * AS_BYTES);
            #pragma unroll
            for (int r = 0; r < 8; r++) {
                int m = mrow + r * 16;
                float* dst = AsN + m * AS_STRIDE + k4 * 4;
                dst[0] = tf32r(fmaxf(areg[r].x + gvn.x, 0.f));
                dst[1] = tf32r(fmaxf(areg[r].y + gvn.y, 0.f));
                dst[2] = tf32r(fmaxf(areg[r].z + gvn.z, 0.f));
                dst[3] = tf32r(fmaxf(areg[r].w + gvn.w, 0.f));
            }
            CPA_WAIT0();
            __syncthreads();
        }
    }

    // ---- epilogue: relu(acc + b2) . W3, reduce n across lanes/warps ----
    #pragma unroll
    for (int mt = 0; mt < 4; mt++) {
        float s0 = 0.f, s1 = 0.f;
        #pragma unroll
        for (int nt = 0; nt < 8; nt++) {
            int n = n0w + nt * 8 + 2 * tig;
            float w0 = w3s[n], w1 = w3s[n + 1];
            float c0 = b2s[n], c1 = b2s[n + 1];
            s0 += fmaxf(acc[mt][nt][0] + c0, 0.f) * w0
                + fmaxf(acc[mt][nt][1] + c1, 0.f) * w1;
            s1 += fmaxf(acc[mt][nt][2] + c0, 0.f) * w0
                + fmaxf(acc[mt][nt][3] + c1, 0.f) * w1;
        }
        s0 += __shfl_xor_sync(0xffffffffu, s0, 1);
        s0 += __shfl_xor_sync(0xffffffffu, s0, 2);
        s1 += __shfl_xor_sync(0xffffffffu, s1, 1);
        s1 += __shfl_xor_sync(0xffffffffu, s1, 2);
        if (tig == 0) {
            red[(m0w + mt * 16 + g) * 4 + nw]     = s0;
            red[(m0w + mt * 16 + g + 8) * 4 + nw] = s1;
        }
    }
    __syncthreads();
    if (tid < 128) {
        float s = red[tid * 4] + red[tid * 4 + 1] + red[tid * 4 + 2] + red[tid * 4 + 3];
        g_scores[i * NHW + j0 + tid] = s + b3p[0];
    }
}

// ---------------------------------------------------------------------------
// finalize (1024 threads per row)
// ---------------------------------------------------------------------------
__global__ __launch_bounds__(1024) void finalize_kernel(float* __restrict__ out) {
    const int i   = blockIdx.x;
    const int tid = threadIdx.x;
    __shared__ float red[1024];
    const float* row = g_scores + i * NHW;

    float mx = -1e30f;
    for (int jj = tid; jj < NHW; jj += 1024) mx = fmaxf(mx, row[jj]);
    red[tid] = mx;
    __syncthreads();
    for (int s = 512; s; s >>= 1) {
        if (tid < s) red[tid] = fmaxf(red[tid], red[tid + s]);
        __syncthreads();
    }
    mx = red[0];
    __syncthreads();

    const int lo = i * HW2, hi = lo + HW2;
    float sum = 0.f;
    for (int jj = tid; jj < NHW; jj += 1024) {
        if (jj < lo || jj >= hi) sum += __expf(row[jj] - mx);
    }
    red[tid] = sum;
    __syncthreads();
    for (int s = 512; s; s >>= 1) {
        if (tid < s) red[tid] += red[tid + s];
        __syncthreads();
    }
    const float neg_mean = red[0] / (float)(NHW - HW2) + EPSC;
    const float lg = __logf(neg_mean);

    for (int p = tid; p < HW2; p += 1024)
        out[i * HW2 + p] = row[lo + p] - mx - lg;
}

// ---------------------------------------------------------------------------
extern "C" void kernel_launch(void* const* d_in, const int* in_sizes, int n_in,
                              void* d_out, int out_size) {
    const float* LF = (const float*)d_in[0];
    const float* GF = (const float*)d_in[1];
    const float* W1 = (const float*)d_in[2];
    const float* b1 = (const float*)d_in[3];
    const float* W2 = (const float*)d_in[4];
    const float* b2 = (const float*)d_in[5];
    const float* W3 = (const float*)d_in[6];
    const float* b3 = (const float*)d_in[7];
    float* out = (float*)d_out;

    static int attr_done = 0;
    if (!attr_done) {
        cudaFuncSetAttribute(score_mma, cudaFuncAttributeMaxDynamicSharedMemorySize, SM_TOTAL);
        attr_done = 1;
    }

    prep_kernel<<<NB + 8, 1024>>>(GF, W1, b1, W2);
    hloc_kernel<<<NHW / 64, 256>>>(LF, W1 + (long)DGLB * HIDN);
    score_mma<<<dim3(NHW / 128, NB), 256, SM_TOTAL>>>(b2, W3, b3);
    finalize_kernel<<<NB, 1024>>>(out);
}

// round 7
// speedup vs baseline: 3.2917x; 1.4123x over previous
#include <cuda_runtime.h>
#include <cuda_fp16.h>
#include <cstdint>

// Problem constants
#define NB    32
#define CLOC  512
#define HW2   196
#define NHW   6272
#define DGLB  2048
#define HIDN  256
#define EPSC  1e-10f

// Scratch (device globals; no allocation allowed)
__device__ float    g_hloc[NHW * HIDN];      // 6.4 MB
__device__ float    g_hglb[NB * HIDN];
__device__ float    g_scores[NB * NHW];      // 0.8 MB
__device__ uint32_t g_W2p[(HIDN / 2) * HIDN]; // W2 packed: [k2][n] = half2(W2[2k2][n], W2[2k2+1][n])

// ---------------------------------------------------------------------------
// helpers
// ---------------------------------------------------------------------------
__device__ __forceinline__ void mma16(float* c, const uint32_t* a,
                                      uint32_t b0, uint32_t b1) {
    asm volatile(
        "mma.sync.aligned.m16n8k16.row.col.f32.f16.f16.f32 "
        "{%0,%1,%2,%3}, {%4,%5,%6,%7}, {%8,%9}, {%0,%1,%2,%3};"
        : "+f"(c[0]), "+f"(c[1]), "+f"(c[2]), "+f"(c[3])
        : "r"(a[0]), "r"(a[1]), "r"(a[2]), "r"(a[3]), "r"(b0), "r"(b1));
}
__device__ __forceinline__ uint32_t smem_u32(const void* p) {
    uint32_t a;
    asm("{ .reg .u64 t; cvta.to.shared.u64 t, %1; cvt.u32.u64 %0, t; }" : "=r"(a) : "l"(p));
    return a;
}
__device__ __forceinline__ void cpa16(uint32_t dst, const void* src) {
    asm volatile("cp.async.ca.shared.global [%0], [%1], 16;" :: "r"(dst), "l"(src));
}
#define CPA_COMMIT() asm volatile("cp.async.commit_group;" ::: "memory")
#define CPA_WAIT0()  asm volatile("cp.async.wait_group 0;" ::: "memory")

// ---------------------------------------------------------------------------
// prep: blocks 0..31 -> h_glb (K-split x4, 1024 thr); blocks 32..39 -> pack W2
// ---------------------------------------------------------------------------
__global__ __launch_bounds__(1024) void prep_kernel(const float* __restrict__ gf,
                                                    const float* __restrict__ W1,
                                                    const float* __restrict__ b1,
                                                    const float* __restrict__ W2) {
    const int tid = threadIdx.x;
    if (blockIdx.x < NB) {
        __shared__ float red[1024];
        const int i  = blockIdx.x;
        const int o  = tid & 255;
        const int kq = tid >> 8;                 // 0..3
        const float* g = gf + i * DGLB + kq * 512;
        const float* w = W1 + (long)(kq * 512) * HIDN + o;
        float s0 = 0.f, s1 = 0.f;
        #pragma unroll 8
        for (int k = 0; k < 512; k += 2) {
            s0 += g[k]     * w[(long)k * HIDN];
            s1 += g[k + 1] * w[(long)(k + 1) * HIDN];
        }
        red[tid] = s0 + s1;
        __syncthreads();
        if (tid < 256)
            g_hglb[i * HIDN + o] = red[tid] + red[tid + 256] + red[tid + 512]
                                 + red[tid + 768] + b1[o];
    } else {
        // pack W2 into k-pair half2 words: g_W2p[k2*256 + n]
        const int idx = (blockIdx.x - NB) * 4096 + tid * 4;
        #pragma unroll
        for (int q = 0; q < 4; q++) {
            int id = idx + q;
            int k2 = id >> 8, n = id & 255;
            __half2 h = __floats2half2_rn(W2[(2 * k2) * HIDN + n],
                                          W2[(2 * k2 + 1) * HIDN + n]);
            g_W2p[id] = *(uint32_t*)&h;
        }
    }
}

// ---------------------------------------------------------------------------
// h_loc = lf @ W1[D:]  (6272 x 512 @ 512 x 256), fp32 SGEMM (exact)
// ---------------------------------------------------------------------------
__global__ __launch_bounds__(256) void hloc_kernel(const float* __restrict__ LF,
                                                   const float* __restrict__ W1loc) {
    __shared__ float As[64][33];
    __shared__ float Bs[32][256];
    const int j0  = blockIdx.x * 64;
    const int tid = threadIdx.x;
    const int tm  = tid >> 5;
    const int tn  = tid & 31;
    const int am  = tid & 63;
    const int akq = tid >> 6;
    const int j   = j0 + am;
    const int n_  = j / HW2;
    const int pos = j % HW2;
    const long abase = (long)n_ * CLOC * HW2 + pos;
    const int bn4 = tid & 63;
    const int bkq = tid >> 6;

    float acc[8][8];
    #pragma unroll
    for (int a = 0; a < 8; a++)
        #pragma unroll
        for (int b = 0; b < 8; b++) acc[a][b] = 0.f;

    for (int kc = 0; kc < CLOC; kc += 32) {
        #pragma unroll
        for (int r = 0; r < 8; r++) {
            int k = akq * 8 + r;
            As[am][k] = LF[abase + (long)(kc + k) * HW2];
        }
        #pragma unroll
        for (int r = 0; r < 8; r++) {
            int k = bkq + 4 * r;
            *(float4*)&Bs[k][bn4 * 4] = *(const float4*)&W1loc[(kc + k) * HIDN + bn4 * 4];
        }
        __syncthreads();
        #pragma unroll
        for (int k = 0; k < 32; k++) {
            float a[8];
            #pragma unroll
            for (int im = 0; im < 8; im++) a[im] = As[tm * 8 + im][k];
            float4 b0 = *(float4*)&Bs[k][tn * 4];
            float4 b1 = *(float4*)&Bs[k][128 + tn * 4];
            #pragma unroll
            for (int im = 0; im < 8; im++) {
                acc[im][0] += a[im] * b0.x; acc[im][1] += a[im] * b0.y;
                acc[im][2] += a[im] * b0.z; acc[im][3] += a[im] * b0.w;
                acc[im][4] += a[im] * b1.x; acc[im][5] += a[im] * b1.y;
                acc[im][6] += a[im] * b1.z; acc[im][7] += a[im] * b1.w;
            }
        }
        __syncthreads();
    }
    #pragma unroll
    for (int im = 0; im < 8; im++) {
        int m = j0 + tm * 8 + im;
        float4 v0 = make_float4(acc[im][0], acc[im][1], acc[im][2], acc[im][3]);
        float4 v1 = make_float4(acc[im][4], acc[im][5], acc[im][6], acc[im][7]);
        *(float4*)&g_hloc[m * HIDN + tn * 4]       = v0;
        *(float4*)&g_hloc[m * HIDN + 128 + tn * 4] = v1;
    }
}

// ---------------------------------------------------------------------------
// score kernel: fp16 m16n8k16 mma.sync (fp32 accumulate; fp16 mantissa ==
// tf32 mantissa so precision matches the old tf32 path at 2x the rate and
// half the LDS/smem traffic). Double-buffered, cp.async-pipelined.
// CTA = (j-tile of 128, i). A[128 x 64k] fp16 = relu(hglb[i]+hloc[j]);
// B = g_W2p chunk (k-pair-packed half2, [k2][n]).
// 8 warps = 2(m) x 4(n); warp tile 64m x 64n = 4 x 8 m16n8k16 tiles.
// ---------------------------------------------------------------------------
#define AS_STRH  72                                 // halves per A row (36 words)
#define AS_BYTES (128 * AS_STRH * 2)                // 18432
#define BS_STRW  264                                // uint32 per B k2-row
#define BS_BYTES (32 * BS_STRW * 4)                 // 33792
#define AS_OFF   0                                  // two buffers
#define BS_OFF   (2 * AS_BYTES)                     // 36864
#define B2_OFF   (BS_OFF + 2 * BS_BYTES)            // 104448
#define W3_OFF   (B2_OFF + 1024)
#define RED_OFF  (W3_OFF + 1024)
#define SM_TOTAL (RED_OFF + 128 * 4 * 4)            // 108544

__global__ __launch_bounds__(256, 1) void score_mma(const float* __restrict__ b2,
                                                    const float* __restrict__ W3,
                                                    const float* __restrict__ b3p) {
    extern __shared__ char smem[];
    float* b2s = (float*)(smem + B2_OFF);
    float* w3s = (float*)(smem + W3_OFF);
    float* red = (float*)(smem + RED_OFF);
    const uint32_t sbase = smem_u32(smem);

    const int tid = threadIdx.x;
    const int wid = tid >> 5, lid = tid & 31;
    const int g   = lid >> 2, tig = lid & 3;
    const int j0  = blockIdx.x * 128;
    const int i   = blockIdx.y;
    const int m0w = (wid & 1) * 64;
    const int nw  = wid >> 1;
    const int n0w = nw * 64;

    b2s[tid] = b2[tid];
    w3s[tid] = W3[tid];

    // fill-phase thread mappings
    const int k4   = tid & 15;                       // A: halves [k4*4 .. k4*4+3]
    const int mrow = tid >> 4;                       // A rows: mrow + r*16
    const int bn4  = tid & 63;                       // B: 16B unit (4 uint32)
    const int bk   = tid >> 6;                       // B k2-rows: bk + r*4

    const float* hl = g_hloc + (long)j0 * HIDN;
    const float* gb = g_hglb + i * HIDN;

    float acc[4][8][4];
    #pragma unroll
    for (int mt = 0; mt < 4; mt++)
        #pragma unroll
        for (int nt = 0; nt < 8; nt++)
            #pragma unroll
            for (int q = 0; q < 4; q++) acc[mt][nt][q] = 0.f;

    // ---- initial fill: chunk 0 into buffer 0 ----
    {
        float4 gv = *(const float4*)(gb + k4 * 4);
        __half* As0 = (__half*)(smem + AS_OFF);
        #pragma unroll
        for (int r = 0; r < 8; r++) {
            int m = mrow + r * 16;
            float4 v = *(const float4*)(hl + (long)m * HIDN + k4 * 4);
            __half2 h01 = __floats2half2_rn(fmaxf(v.x + gv.x, 0.f), fmaxf(v.y + gv.y, 0.f));
            __half2 h23 = __floats2half2_rn(fmaxf(v.z + gv.z, 0.f), fmaxf(v.w + gv.w, 0.f));
            uint2 pk = make_uint2(*(uint32_t*)&h01, *(uint32_t*)&h23);
            *(uint2*)(As0 + m * AS_STRH + k4 * 4) = pk;
        }
        #pragma unroll
        for (int r = 0; r < 8; r++) {
            int k2 = bk + r * 4;
            cpa16(sbase + BS_OFF + k2 * (BS_STRW * 4) + bn4 * 16,
                  g_W2p + (long)k2 * HIDN + bn4 * 4);
        }
        CPA_COMMIT();
        CPA_WAIT0();
        __syncthreads();
    }

    for (int c = 0; c < 4; c++) {
        const int pb = c & 1, nb = pb ^ 1;
        const uint32_t* AsU = (const uint32_t*)(smem + AS_OFF + pb * AS_BYTES);
        const uint32_t* BsU = (const uint32_t*)(smem + BS_OFF + pb * BS_BYTES);

        // ---- prefetch next chunk: A -> regs (LDG), B -> smem (cp.async) ----
        float4 areg[8];
        float4 gvn;
        if (c < 3) {
            const int kb = (c + 1) * 64;
            gvn = *(const float4*)(gb + kb + k4 * 4);
            #pragma unroll
            for (int r = 0; r < 8; r++) {
                int m = mrow + r * 16;
                areg[r] = *(const float4*)(hl + (long)m * HIDN + kb + k4 * 4);
            }
            #pragma unroll
            for (int r = 0; r < 8; r++) {
                int k2 = bk + r * 4;
                cpa16(sbase + BS_OFF + nb * BS_BYTES + k2 * (BS_STRW * 4) + bn4 * 16,
                      g_W2p + (long)((c + 1) * 32 + k2) * HIDN + bn4 * 4);
            }
            CPA_COMMIT();
        }

        // ---- mma phase on current buffers: 4 k16 steps per 64-k chunk ----
        #pragma unroll
        for (int kk = 0; kk < 4; kk++) {
            const int kw  = kk * 8;                  // word offset in A row
            const int k2b = kk * 8;                  // k2-row base in B
            uint32_t a[4][4];
            #pragma unroll
            for (int mt = 0; mt < 4; mt++) {
                int mr = m0w + mt * 16 + g;
                a[mt][0] = AsU[mr * 36 + kw + tig];
                a[mt][1] = AsU[(mr + 8) * 36 + kw + tig];
                a[mt][2] = AsU[mr * 36 + kw + tig + 4];
                a[mt][3] = AsU[(mr + 8) * 36 + kw + tig + 4];
            }
            #pragma unroll
            for (int nt = 0; nt < 8; nt++) {
                int nc = n0w + nt * 8 + g;
                uint32_t b0 = BsU[(k2b + tig) * BS_STRW + nc];
                uint32_t b1 = BsU[(k2b + tig + 4) * BS_STRW + nc];
                #pragma unroll
                for (int mt = 0; mt < 4; mt++)
                    mma16(acc[mt][nt], a[mt], b0, b1);
            }
        }

        // ---- store prefetched A into next buffer; wait B; barrier ----
        if (c < 3) {
            __half* AsN = (__half*)(smem + AS_OFF + nb * AS_BYTES);
            #pragma unroll
            for (int r = 0; r < 8; r++) {
                int m = mrow + r * 16;
                __half2 h01 = __floats2half2_rn(fmaxf(areg[r].x + gvn.x, 0.f),
                                                fmaxf(areg[r].y + gvn.y, 0.f));
                __half2 h23 = __floats2half2_rn(fmaxf(areg[r].z + gvn.z, 0.f),
                                                fmaxf(areg[r].w + gvn.w, 0.f));
                uint2 pk = make_uint2(*(uint32_t*)&h01, *(uint32_t*)&h23);
                *(uint2*)(AsN + m * AS_STRH + k4 * 4) = pk;
            }
            CPA_WAIT0();
            __syncthreads();
        }
    }

    // ---- epilogue: relu(acc + b2) . W3, reduce n across lanes/warps ----
    #pragma unroll
    for (int mt = 0; mt < 4; mt++) {
        float s0 = 0.f, s1 = 0.f;
        #pragma unroll
        for (int nt = 0; nt < 8; nt++) {
            int n = n0w + nt * 8 + 2 * tig;
            float w0 = w3s[n], w1 = w3s[n + 1];
            float c0 = b2s[n], c1 = b2s[n + 1];
            s0 += fmaxf(acc[mt][nt][0] + c0, 0.f) * w0
                + fmaxf(acc[mt][nt][1] + c1, 0.f) * w1;
            s1 += fmaxf(acc[mt][nt][2] + c0, 0.f) * w0
                + fmaxf(acc[mt][nt][3] + c1, 0.f) * w1;
        }
        s0 += __shfl_xor_sync(0xffffffffu, s0, 1);
        s0 += __shfl_xor_sync(0xffffffffu, s0, 2);
        s1 += __shfl_xor_sync(0xffffffffu, s1, 1);
        s1 += __shfl_xor_sync(0xffffffffu, s1, 2);
        if (tig == 0) {
            red[(m0w + mt * 16 + g) * 4 + nw]     = s0;
            red[(m0w + mt * 16 + g + 8) * 4 + nw] = s1;
        }
    }
    __syncthreads();
    if (tid < 128) {
        float s = red[tid * 4] + red[tid * 4 + 1] + red[tid * 4 + 2] + red[tid * 4 + 3];
        g_scores[i * NHW + j0 + tid] = s + b3p[0];
    }
}

// ---------------------------------------------------------------------------
// finalize (1024 threads per row)
// ---------------------------------------------------------------------------
__global__ __launch_bounds__(1024) void finalize_kernel(float* __restrict__ out) {
    const int i   = blockIdx.x;
    const int tid = threadIdx.x;
    __shared__ float red[1024];
    const float* row = g_scores + i * NHW;

    float mx = -1e30f;
    for (int jj = tid; jj < NHW; jj += 1024) mx = fmaxf(mx, row[jj]);
    red[tid] = mx;
    __syncthreads();
    for (int s = 512; s; s >>= 1) {
        if (tid < s) red[tid] = fmaxf(red[tid], red[tid + s]);
        __syncthreads();
    }
    mx = red[0];
    __syncthreads();

    const int lo = i * HW2, hi = lo + HW2;
    float sum = 0.f;
    for (int jj = tid; jj < NHW; jj += 1024) {
        if (jj < lo || jj >= hi) sum += __expf(row[jj] - mx);
    }
    red[tid] = sum;
    __syncthreads();
    for (int s = 512; s; s >>= 1) {
        if (tid < s) red[tid] += red[tid + s];
        __syncthreads();
    }
    const float neg_mean = red[0] / (float)(NHW - HW2) + EPSC;
    const float lg = __logf(neg_mean);

    for (int p = tid; p < HW2; p += 1024)
        out[i * HW2 + p] = row[lo + p] - mx - lg;
}

// ---------------------------------------------------------------------------
extern "C" void kernel_launch(void* const* d_in, const int* in_sizes, int n_in,
                              void* d_out, int out_size) {
    const float* LF = (const float*)d_in[0];
    const float* GF = (const float*)d_in[1];
    const float* W1 = (const float*)d_in[2];
    const float* b1 = (const float*)d_in[3];
    const float* W2 = (const float*)d_in[4];
    const float* b2 = (const float*)d_in[5];
    const float* W3 = (const float*)d_in[6];
    const float* b3 = (const float*)d_in[7];
    float* out = (float*)d_out;

    static int attr_done = 0;
    if (!attr_done) {
        cudaFuncSetAttribute(score_mma, cudaFuncAttributeMaxDynamicSharedMemorySize, SM_TOTAL);
        attr_done = 1;
    }

    prep_kernel<<<NB + 8, 1024>>>(GF, W1, b1, W2);
    hloc_kernel<<<NHW / 64, 256>>>(LF, W1 + (long)DGLB * HIDN);
    score_mma<<<dim3(NHW / 128, NB), 256, SM_TOTAL>>>(b2, W3, b3);
    finalize_kernel<<<NB, 1024>>>(out);
}